// round 11
// baseline (speedup 1.0000x reference)
#include <cuda_runtime.h>

#define NTIME 1024
#define NB    65536
#define TPB   128   // 4 warps/block; 16 batches per warp (2 lanes per batch)

// L2 evict-last via cache-policy form (scalar evict_last qualifier is illegal
// on this ptxas; the createpolicy + cache_hint form is the supported path).
__device__ __forceinline__ unsigned long long mk_evict_last_policy()
{
    unsigned long long pol;
    asm("createpolicy.fractional.L2::evict_last.b64 %0, 1.0;" : "=l"(pol));
    return pol;
}

__device__ __forceinline__ float ldg_el(const float* p, unsigned long long pol)
{
    float v;
    asm volatile("ld.global.nc.L2::cache_hint.f32 %0, [%1], %2;"
                 : "=f"(v) : "l"(p), "l"(pol));
    return v;
}

__device__ __forceinline__ float sel3(float x0, float x1, float x2, int i)
{
    const float a = (i & 1) ? x1 : x0;
    return (i & 2) ? x2 : a;
}

__global__ void __launch_bounds__(TPB)
bts_interp_kernel(const float* __restrict__ times,
                  const float* __restrict__ values,
                  const float* __restrict__ tq,
                  float* __restrict__ out)
{
    const unsigned FULL = 0xFFFFFFFFu;
    const int lane = threadIdx.x & 31;
    const int warp = threadIdx.x >> 5;
    const int half = lane >> 4;                       // 0 = lower pair half
    const int b    = blockIdx.x * 64 + warp * 16 + (lane & 15);

    const unsigned long long pol = mk_evict_last_policy();

    const float t = ldg_el(&tq[b], pol);
    const float* col = times + b;

    // ── Coarse (split): 64 rows 15,31,...,1023; half h scans coarse idx h*32..h*32+31.
    int   m_h  = 0;
    float lo_h = 0.0f, hi_h = 0.0f;
#pragma unroll
    for (int chunk = 0; chunk < 4; ++chunk) {
        float x[8];
#pragma unroll
        for (int i = 0; i < 8; ++i) {
            const int j = half * 32 + chunk * 8 + i;          // coarse index 0..63
            x[i] = ldg_el(col + (size_t)(16 * j + 15) * NB, pol);
        }
#pragma unroll
        for (int i = 0; i < 8; ++i) {
            const int jl = chunk * 8 + i;                     // local 0..31 (sorted prefix)
            if (x[i] <= t) { lo_h = x[i]; m_h++; }
            else if (jl == m_h) hi_h = x[i];                  // first local failure
        }
    }

    // Merge halves (sorted column => any upper-half success implies lower half full).
    const int   m_o  = __shfl_xor_sync(FULL, m_h,  16);
    const float lo_o = __shfl_xor_sync(FULL, lo_h, 16);
    const float hi_o = __shfl_xor_sync(FULL, hi_h, 16);
    const int   m0 = half ? m_o  : m_h;
    const int   m1 = half ? m_h  : m_o;
    const float lo0 = half ? lo_o : lo_h;
    const float lo1 = half ? lo_h : lo_o;
    const float hi0 = half ? hi_o : hi_h;
    const float hi1 = half ? hi_h : hi_o;

    const int m = m0 + m1;
    float lo = (m1 > 0)  ? lo1 : lo0;   // = times[16m-1]  (valid iff m > 0)
    float hi = (m0 < 32) ? hi0 : hi1;   // = times[16m+15] (valid iff m < 64)

    int c = m << 4;                     // count in [c, c+15]
    const bool hiwrap = (m == 64);      // count == 1024 (both pair halves agree)

    // ── Round 2 (split 2/1): probe rows c+3, c+7, c+11. ──
    {
        int r0 = c + 3, r1 = c + 7, r2 = c + 11;
        if (hiwrap) { r0 = r1 = r2 = NTIME - 1; }   // in-bounds; result discarded
        float pa, pb = 0.0f;
        if (half == 0) { pa = ldg_el(col + (size_t)r0 * NB, pol);
                         pb = ldg_el(col + (size_t)r2 * NB, pol); }
        else           { pa = ldg_el(col + (size_t)r1 * NB, pol); }
        const float ea = __shfl_xor_sync(FULL, pa, 16);
        const float eb = __shfl_xor_sync(FULL, pb, 16);
        const float p0 = half ? ea : pa;
        const float p1 = half ? pa : ea;
        const float p2 = half ? eb : pb;
        const int s = ((p0 <= t) ? 1 : 0) + ((p1 <= t) ? 1 : 0) + ((p2 <= t) ? 1 : 0);
        if (s > 0) lo = sel3(p0, p1, p2, s - 1);
        if (s < 3) hi = sel3(p0, p1, p2, s);
        c += 4 * s;                     // count in [c, c+3]
    }

    // ── Round 3 (split 2/1): probe rows c, c+1, c+2. ──
    {
        int r0 = c, r1 = c + 1, r2 = c + 2;
        if (hiwrap) { r0 = r1 = r2 = NTIME - 1; }
        float qa, qb = 0.0f;
        if (half == 0) { qa = ldg_el(col + (size_t)r0 * NB, pol);
                         qb = ldg_el(col + (size_t)r2 * NB, pol); }
        else           { qa = ldg_el(col + (size_t)r1 * NB, pol); }
        const float ea = __shfl_xor_sync(FULL, qa, 16);
        const float eb = __shfl_xor_sync(FULL, qb, 16);
        const float q0 = half ? ea : qa;
        const float q1 = half ? qa : ea;
        const float q2 = half ? eb : qb;
        const int s2 = ((q0 <= t) ? 1 : 0) + ((q1 <= t) ? 1 : 0) + ((q2 <= t) ? 1 : 0);
        if (s2 > 0) lo = sel3(q0, q1, q2, s2 - 1);  // times[c-1] (exact)
        if (s2 < 3) hi = sel3(q0, q1, q2, s2);      // times[c]   (exact)
        c += s2;                                    // exact count (when !hiwrap)
    }

    // ── Values (split 1/1): rows c-1 / c, BOTH clamped to [0, NTIME-1].
    int ia = c - 1;
    if (ia < 0)         ia = 0;
    if (ia > NTIME - 1) ia = NTIME - 1;
    int ib = c;
    if (ib > NTIME - 1) ib = NTIME - 1;

    float v_mine;
    if (half == 0) v_mine = ldg_el(&values[(size_t)ia * NB + b], pol);
    else           v_mine = ldg_el(&values[(size_t)ib * NB + b], pol);
    const float v_oth = __shfl_xor_sync(FULL, v_mine, 16);

    if (half == 0) {
        const bool wrap = hiwrap || (c == 0);       // count == 1024 or 0
        float result;
        if (!wrap) {
            const float va = v_mine;                // values[c-1]
            const float vb = v_oth;                 // values[c]
            const float s0 = (vb - va) / (hi - lo); // lo/hi bit-exact bracket knots
            result = va + s0 * (t - lo);
        } else {
            // Reference wrap: iv = 1023, isl = 1022.
            const float tp = ldg_el(&times [(size_t)(NTIME - 2) * NB + b], pol);
            const float tl = ldg_el(&times [(size_t)(NTIME - 1) * NB + b], pol);
            const float vp = ldg_el(&values[(size_t)(NTIME - 2) * NB + b], pol);
            const float vl = ldg_el(&values[(size_t)(NTIME - 1) * NB + b], pol);
            const float s0 = (vl - vp) / (tl - tp);
            result = vl + s0 * (t - tl);
        }
        out[b] = result;
    }
}

extern "C" void kernel_launch(void* const* d_in, const int* in_sizes, int n_in,
                              void* d_out, int out_size)
{
    const float* times  = (const float*)d_in[0];
    const float* values = (const float*)d_in[1];
    const float* tq     = (const float*)d_in[2];
    float* out = (float*)d_out;

    // 2 threads per batch: 131072 threads, 1024 blocks of 128.
    bts_interp_kernel<<<(NB * 2) / TPB, TPB>>>(times, values, tq, out);
}

// round 12
// speedup vs baseline: 1.0029x; 1.0029x over previous
#include <cuda_runtime.h>

#define NTIME 1024
#define NB    65536
#define TPB   128   // 4 warps/block; 16 batches per warp (2 lanes per batch)

// Plain global load (generic LSU path, sector-granular L2/DRAM fill) for the
// scattered probes. The __ldg/.nc constant path can over-fetch the full 128B
// line; these loads use 4B of the line, so request only the 32B sector.
__device__ __forceinline__ float ldg_plain(const float* p)
{
    float v;
    asm volatile("ld.global.f32 %0, [%1];" : "=f"(v) : "l"(p));
    return v;
}

__device__ __forceinline__ float sel3(float x0, float x1, float x2, int i)
{
    const float a = (i & 1) ? x1 : x0;
    return (i & 2) ? x2 : a;
}

__global__ void __launch_bounds__(TPB)
bts_interp_kernel(const float* __restrict__ times,
                  const float* __restrict__ values,
                  const float* __restrict__ tq,
                  float* __restrict__ out)
{
    const unsigned FULL = 0xFFFFFFFFu;
    const int lane = threadIdx.x & 31;
    const int warp = threadIdx.x >> 5;
    const int half = lane >> 4;                       // 0 = lower pair half
    const int b    = blockIdx.x * 64 + warp * 16 + (lane & 15);

    const float t = __ldg(&tq[b]);
    const float* col = times + b;

    // ── Coarse (split, coalesced — keep __ldg, lines fully consumed):
    // 64 rows 15,31,...,1023; half h scans coarse idx h*32..h*32+31.
    int   m_h  = 0;
    float lo_h = 0.0f, hi_h = 0.0f;
#pragma unroll
    for (int chunk = 0; chunk < 4; ++chunk) {
        float x[8];
#pragma unroll
        for (int i = 0; i < 8; ++i) {
            const int j = half * 32 + chunk * 8 + i;          // coarse index 0..63
            x[i] = __ldg(col + (size_t)(16 * j + 15) * NB);
        }
#pragma unroll
        for (int i = 0; i < 8; ++i) {
            const int jl = chunk * 8 + i;                     // local 0..31 (sorted prefix)
            if (x[i] <= t) { lo_h = x[i]; m_h++; }
            else if (jl == m_h) hi_h = x[i];                  // first local failure
        }
    }

    // Merge halves (sorted column => any upper-half success implies lower half full).
    const int   m_o  = __shfl_xor_sync(FULL, m_h,  16);
    const float lo_o = __shfl_xor_sync(FULL, lo_h, 16);
    const float hi_o = __shfl_xor_sync(FULL, hi_h, 16);
    const int   m0 = half ? m_o  : m_h;
    const int   m1 = half ? m_h  : m_o;
    const float lo0 = half ? lo_o : lo_h;
    const float lo1 = half ? lo_h : lo_o;
    const float hi0 = half ? hi_o : hi_h;
    const float hi1 = half ? hi_h : hi_o;

    const int m = m0 + m1;
    float lo = (m1 > 0)  ? lo1 : lo0;   // = times[16m-1]  (valid iff m > 0)
    float hi = (m0 < 32) ? hi0 : hi1;   // = times[16m+15] (valid iff m < 64)

    int c = m << 4;                     // count in [c, c+15]
    const bool hiwrap = (m == 64);      // count == 1024 (both pair halves agree)

    // ── Round 2 (split 2/1, sector loads): probe rows c+3, c+7, c+11. ──
    {
        int r0 = c + 3, r1 = c + 7, r2 = c + 11;
        if (hiwrap) { r0 = r1 = r2 = NTIME - 1; }   // in-bounds; result discarded
        float pa, pb = 0.0f;
        if (half == 0) { pa = ldg_plain(col + (size_t)r0 * NB);
                         pb = ldg_plain(col + (size_t)r2 * NB); }
        else           { pa = ldg_plain(col + (size_t)r1 * NB); }
        const float ea = __shfl_xor_sync(FULL, pa, 16);
        const float eb = __shfl_xor_sync(FULL, pb, 16);
        const float p0 = half ? ea : pa;
        const float p1 = half ? pa : ea;
        const float p2 = half ? eb : pb;
        const int s = ((p0 <= t) ? 1 : 0) + ((p1 <= t) ? 1 : 0) + ((p2 <= t) ? 1 : 0);
        if (s > 0) lo = sel3(p0, p1, p2, s - 1);
        if (s < 3) hi = sel3(p0, p1, p2, s);
        c += 4 * s;                     // count in [c, c+3]
    }

    // ── Round 3 (split 2/1, sector loads): probe rows c, c+1, c+2. ──
    {
        int r0 = c, r1 = c + 1, r2 = c + 2;
        if (hiwrap) { r0 = r1 = r2 = NTIME - 1; }
        float qa, qb = 0.0f;
        if (half == 0) { qa = ldg_plain(col + (size_t)r0 * NB);
                         qb = ldg_plain(col + (size_t)r2 * NB); }
        else           { qa = ldg_plain(col + (size_t)r1 * NB); }
        const float ea = __shfl_xor_sync(FULL, qa, 16);
        const float eb = __shfl_xor_sync(FULL, qb, 16);
        const float q0 = half ? ea : qa;
        const float q1 = half ? qa : ea;
        const float q2 = half ? eb : qb;
        const int s2 = ((q0 <= t) ? 1 : 0) + ((q1 <= t) ? 1 : 0) + ((q2 <= t) ? 1 : 0);
        if (s2 > 0) lo = sel3(q0, q1, q2, s2 - 1);  // times[c-1] (exact)
        if (s2 < 3) hi = sel3(q0, q1, q2, s2);      // times[c]   (exact)
        c += s2;                                    // exact count (when !hiwrap)
    }

    // ── Values (split 1/1, sector loads): rows c-1 / c, clamped to [0, NTIME-1].
    int ia = c - 1;
    if (ia < 0)         ia = 0;
    if (ia > NTIME - 1) ia = NTIME - 1;
    int ib = c;
    if (ib > NTIME - 1) ib = NTIME - 1;

    float v_mine;
    if (half == 0) v_mine = ldg_plain(&values[(size_t)ia * NB + b]);
    else           v_mine = ldg_plain(&values[(size_t)ib * NB + b]);
    const float v_oth = __shfl_xor_sync(FULL, v_mine, 16);

    if (half == 0) {
        const bool wrap = hiwrap || (c == 0);       // count == 1024 or 0
        float result;
        if (!wrap) {
            const float va = v_mine;                // values[c-1]
            const float vb = v_oth;                 // values[c]
            const float s0 = (vb - va) / (hi - lo); // lo/hi bit-exact bracket knots
            result = va + s0 * (t - lo);
        } else {
            // Reference wrap: iv = 1023, isl = 1022.
            const float tp = ldg_plain(&times [(size_t)(NTIME - 2) * NB + b]);
            const float tl = ldg_plain(&times [(size_t)(NTIME - 1) * NB + b]);
            const float vp = ldg_plain(&values[(size_t)(NTIME - 2) * NB + b]);
            const float vl = ldg_plain(&values[(size_t)(NTIME - 1) * NB + b]);
            const float s0 = (vl - vp) / (tl - tp);
            result = vl + s0 * (t - tl);
        }
        out[b] = result;
    }
}

extern "C" void kernel_launch(void* const* d_in, const int* in_sizes, int n_in,
                              void* d_out, int out_size)
{
    const float* times  = (const float*)d_in[0];
    const float* values = (const float*)d_in[1];
    const float* tq     = (const float*)d_in[2];
    float* out = (float*)d_out;

    // 2 threads per batch: 131072 threads, 1024 blocks of 128.
    bts_interp_kernel<<<(NB * 2) / TPB, TPB>>>(times, values, tq, out);
}